// round 3
// baseline (speedup 1.0000x reference)
#include <cuda_runtime.h>

// Problem constants
#define NB   2
#define NN   512
#define DDIM 128
#define HH   8
#define DKK  16

// Scratch (device globals — no allocation allowed)
__device__ float g_qkv [NB*NN*384];              // [b, tok, {q,k,v}, h, dk] = [bn][384]
__device__ float g_Ebuf[NB*NN*NN*HH];            // _E, layout [b][n][m][h]  (16 MB)
__device__ float g_dyn [NB*HH*NN];               // log1p(sum_m G)  [b][h][n]
__device__ float g_nmid[NB*NN*DDIM];             // (A@V)*dyn_cent, [b][n][h][dk]

// ---------------------------------------------------------------------------
// Kernel 1: qkv = n @ W_qkv   (1024 x 384 x 128)
// block = 8 rows, 384 threads (one output column each)
// ---------------------------------------------------------------------------
__global__ void __launch_bounds__(384) qkv_kernel(const float* __restrict__ nin,
                                                  const float* __restrict__ Wqkv)
{
    __shared__ float sA[8*128];
    const int tid = threadIdx.x;
    const int r0  = blockIdx.x * 8;
    for (int i = tid; i < 1024; i += 384) sA[i] = nin[(size_t)r0*128 + i];
    __syncthreads();
    float acc[8] = {0,0,0,0,0,0,0,0};
    const int c = tid;
#pragma unroll 4
    for (int d = 0; d < 128; d++) {
        const float wv = Wqkv[d*384 + c];
#pragma unroll
        for (int r = 0; r < 8; r++) acc[r] += sA[r*128 + d] * wv;
    }
#pragma unroll
    for (int r = 0; r < 8; r++) g_qkv[(size_t)(r0 + r)*384 + c] = acc[r];
}

// ---------------------------------------------------------------------------
// Kernel 2: fused edge pass.  One block per (b,n); 8 warps; each lane-quad
// owns one m-row (lane = r*4 + q : r = row-in-group, q = 32-float d-slice).
// Per row (512B of e read once):
//   E[h] = e_row . W_e[:,h], G[h] = sigmoid(e_row . W_g[:,h])
//   araw[h] = Q[b,n,h,:] . K[b,m,h,:]   (head slice fully inside one lane)
//   _E[h] = clip(araw*0.25) + E[h]  -> g_Ebuf  (L2-resident scratch)
//   e_out row = sum_h _E[h] * O_e[h,:]  -> streaming store (bypass-ish L2)
//   Gsum[b,h,n] += G[h]
// ---------------------------------------------------------------------------
__global__ void __launch_bounds__(256) edge_kernel(const float* __restrict__ e,
                                                   const float* __restrict__ Wg,
                                                   const float* __restrict__ We,
                                                   const float* __restrict__ Oe,
                                                   float* __restrict__ eout)
{
    // W_e/W_g in smem, split per d-slice (q) with 8-float pad per group so the
    // four q-slices land on different bank quads (stride 264 = 8*33 words).
    __shared__ float sWe[4*264];
    __shared__ float sWg[4*264];
    __shared__ float sOe[1024];     // [h][d], identical to global layout
    __shared__ float sGsum[8];

    const int tid = threadIdx.x;
    const int bn  = blockIdx.x;           // b*512 + n
    const int b   = bn >> 9;

    for (int i = tid; i < 1024; i += 256) {
        const int d = i >> 3, h = i & 7;
        const int qg = d >> 5, dl = d & 31;
        sWe[qg*264 + dl*8 + h] = We[i];   // We[d][h], i = d*8+h
        sWg[qg*264 + dl*8 + h] = Wg[i];
        sOe[i] = Oe[i];                   // Oe[h][d], i = h*128+d
    }
    if (tid < 8) sGsum[tid] = 0.f;
    __syncthreads();

    const int lane = tid & 31, w = tid >> 5;
    const int q = lane & 3;               // d-slice [q*32, q*32+32)
    const int r = lane >> 2;              // row within 8-row group

    // Q slice for this lane (fixed for whole block): heads 2q, 2q+1
    const float* qp = g_qkv + (size_t)bn*384 + q*32;
    float4 qreg[8];
#pragma unroll
    for (int j = 0; j < 8; j++) qreg[j] = *(const float4*)(qp + j*4);

    float gs[8] = {0,0,0,0,0,0,0,0};

    for (int t = 0; t < 8; t++) {
        const int m = t*64 + w*8 + r;
        const float4* ep = (const float4*)(e + ((size_t)bn*NN + m)*DDIM + q*32);
        const float4* kp = (const float4*)(g_qkv + (size_t)(b*NN + m)*384 + 128 + q*32);

        float accE[8] = {0,0,0,0,0,0,0,0};
        float accG[8] = {0,0,0,0,0,0,0,0};
        float a0 = 0.f, a1 = 0.f;   // QK partials: heads 2q (j<4) and 2q+1 (j>=4)

#pragma unroll
        for (int j = 0; j < 8; j++) {
            const float4 ev = __ldcs(ep + j);   // e streamed once: .cs
            const float4 kv = kp[j];
            const float4 qv = qreg[j];
            const float aa = qv.x*kv.x + qv.y*kv.y + qv.z*kv.z + qv.w*kv.w;
            if (j < 4) a0 += aa; else a1 += aa;

            const float ev4[4] = {ev.x, ev.y, ev.z, ev.w};
#pragma unroll
            for (int rr = 0; rr < 4; rr++) {
                const float evr = ev4[rr];
                const float4* wb = (const float4*)(sWe + q*264 + (j*4+rr)*8);
                const float4 w0 = wb[0], w1 = wb[1];
                accE[0] += evr*w0.x; accE[1] += evr*w0.y;
                accE[2] += evr*w0.z; accE[3] += evr*w0.w;
                accE[4] += evr*w1.x; accE[5] += evr*w1.y;
                accE[6] += evr*w1.z; accE[7] += evr*w1.w;
                const float4* gb = (const float4*)(sWg + q*264 + (j*4+rr)*8);
                const float4 g0 = gb[0], g1 = gb[1];
                accG[0] += evr*g0.x; accG[1] += evr*g0.y;
                accG[2] += evr*g0.z; accG[3] += evr*g0.w;
                accG[4] += evr*g1.x; accG[5] += evr*g1.y;
                accG[6] += evr*g1.z; accG[7] += evr*g1.w;
            }
        }

        // reduce over the 4 lanes of the quad (xor 1, xor 2): every quad lane
        // ends with the full 8 E and 8 G sums for its row.
#pragma unroll
        for (int k = 0; k < 8; k++) {
            accE[k] += __shfl_xor_sync(0xffffffffu, accE[k], 1);
            accE[k] += __shfl_xor_sync(0xffffffffu, accE[k], 2);
            accG[k] += __shfl_xor_sync(0xffffffffu, accG[k], 1);
            accG[k] += __shfl_xor_sync(0xffffffffu, accG[k], 2);
        }

        // gather araw for all 8 heads (source lane = same quad, q = h>>1)
        float Ef[8];
#pragma unroll
        for (int h = 0; h < 8; h++) {
            const float ar = __shfl_sync(0xffffffffu, (h & 1) ? a1 : a0,
                                         (lane & ~3) | (h >> 1));
            Ef[h] = fminf(fmaxf(ar * 0.25f, -5.f), 5.f) + accE[h];
        }

        if (q == 0) {
            float4* eb = (float4*)(g_Ebuf + ((size_t)bn*NN + m)*8);
            eb[0] = make_float4(Ef[0], Ef[1], Ef[2], Ef[3]);
            eb[1] = make_float4(Ef[4], Ef[5], Ef[6], Ef[7]);
#pragma unroll
            for (int h = 0; h < 8; h++)
                gs[h] += 1.f / (1.f + __expf(-accG[h]));
        }

        // e_out row slice: 32 floats = _E . O_e[:, q*32 .. q*32+32)
        float4* eo = (float4*)(eout + ((size_t)bn*NN + m)*DDIM + q*32);
#pragma unroll
        for (int j = 0; j < 8; j++) {
            const float* ob = sOe + q*32 + j*4;
            float4 o = make_float4(0.f, 0.f, 0.f, 0.f);
#pragma unroll
            for (int h = 0; h < 8; h++) {
                const float4 ov = *(const float4*)(ob + h*128);
                o.x += Ef[h]*ov.x; o.y += Ef[h]*ov.y;
                o.z += Ef[h]*ov.z; o.w += Ef[h]*ov.w;
            }
            __stcs(eo + j, o);              // streaming store: don't pollute L2
        }
    }

    if (q == 0) {
#pragma unroll
        for (int h = 0; h < 8; h++) atomicAdd(&sGsum[h], gs[h]);
    }
    __syncthreads();
    if (tid < 8) {
        const int n = bn & 511;
        g_dyn[(b*8 + tid)*NN + n] = log1pf(sGsum[tid]);
    }
}

// ---------------------------------------------------------------------------
// Kernel 3: softmax(_E) @ V, scaled by dyn_cent.  Block per (b,n), warp per h.
// ---------------------------------------------------------------------------
__global__ void __launch_bounds__(256) attn_kernel()
{
    __shared__ float sE[8*520];   // [h][m], padded row
    const int tid = threadIdx.x, bn = blockIdx.x;
    const int b = bn >> 9, n = bn & 511;

    const float4* Eb = (const float4*)(g_Ebuf + (size_t)bn*4096);
    for (int i = tid; i < 1024; i += 256) {
        const float4 v = Eb[i];
        const int m = i >> 1, h0 = (i & 1) * 4;
        sE[(h0+0)*520 + m] = v.x;
        sE[(h0+1)*520 + m] = v.y;
        sE[(h0+2)*520 + m] = v.z;
        sE[(h0+3)*520 + m] = v.w;
    }
    __syncthreads();

    const int h = tid >> 5, lane = tid & 31;
    float x[16];
#pragma unroll
    for (int k = 0; k < 16; k++) x[k] = sE[h*520 + lane + k*32];

    float mx = x[0];
#pragma unroll
    for (int k = 1; k < 16; k++) mx = fmaxf(mx, x[k]);
#pragma unroll
    for (int off = 16; off > 0; off >>= 1)
        mx = fmaxf(mx, __shfl_xor_sync(0xffffffffu, mx, off));

    float p[16]; float s = 0.f;
#pragma unroll
    for (int k = 0; k < 16; k++) { p[k] = __expf(x[k] - mx); s += p[k]; }
#pragma unroll
    for (int off = 16; off > 0; off >>= 1)
        s += __shfl_xor_sync(0xffffffffu, s, off);

    float o[16];
#pragma unroll
    for (int k = 0; k < 16; k++) o[k] = 0.f;

    const float* Vb = g_qkv + (size_t)b*NN*384 + 256 + h*16;
#pragma unroll
    for (int k = 0; k < 16; k++) {
        const float4* vp = (const float4*)(Vb + (size_t)(lane + k*32)*384);
        const float4 v0 = vp[0], v1 = vp[1], v2 = vp[2], v3 = vp[3];
        const float pk = p[k];
        o[0]  += pk*v0.x; o[1]  += pk*v0.y; o[2]  += pk*v0.z; o[3]  += pk*v0.w;
        o[4]  += pk*v1.x; o[5]  += pk*v1.y; o[6]  += pk*v1.z; o[7]  += pk*v1.w;
        o[8]  += pk*v2.x; o[9]  += pk*v2.y; o[10] += pk*v2.z; o[11] += pk*v2.w;
        o[12] += pk*v3.x; o[13] += pk*v3.y; o[14] += pk*v3.z; o[15] += pk*v3.w;
    }
#pragma unroll
    for (int off = 16; off > 0; off >>= 1) {
#pragma unroll
        for (int d2 = 0; d2 < 16; d2++)
            o[d2] += __shfl_xor_sync(0xffffffffu, o[d2], off);
    }
    if (lane == 0) {
        const float dc = g_dyn[(b*8 + h)*NN + n];
        const float sc = dc / s;
        float* np = g_nmid + (size_t)bn*128 + h*16;
#pragma unroll
        for (int d2 = 0; d2 < 16; d2++) np[d2] = o[d2] * sc;
    }
}

// ---------------------------------------------------------------------------
// Kernel 4: n_out = n_mid @ O_n   (1024 x 128 x 128)
// ---------------------------------------------------------------------------
__global__ void __launch_bounds__(128) nout_kernel(const float* __restrict__ On,
                                                   float* __restrict__ out)
{
    __shared__ float sA[8*128];
    const int tid = threadIdx.x;
    const int r0  = blockIdx.x * 8;
    for (int i = tid; i < 1024; i += 128) sA[i] = g_nmid[(size_t)r0*128 + i];
    __syncthreads();
    float acc[8] = {0,0,0,0,0,0,0,0};
#pragma unroll 4
    for (int d = 0; d < 128; d++) {
        const float wv = On[d*128 + tid];
#pragma unroll
        for (int r = 0; r < 8; r++) acc[r] += sA[r*128 + d] * wv;
    }
#pragma unroll
    for (int r = 0; r < 8; r++) out[(size_t)(r0 + r)*128 + tid] = acc[r];
}

// ---------------------------------------------------------------------------
// Launch: inputs in metadata order: n, e, W_qkv, O_n, W_g, W_e, O_e
// Output: n_out (B*N*D floats) followed by e_out (B*N*N*D floats)
// ---------------------------------------------------------------------------
extern "C" void kernel_launch(void* const* d_in, const int* in_sizes, int n_in,
                              void* d_out, int out_size)
{
    const float* n_in_p = (const float*)d_in[0];
    const float* e_p    = (const float*)d_in[1];
    const float* Wqkv_p = (const float*)d_in[2];
    const float* On_p   = (const float*)d_in[3];
    const float* Wg_p   = (const float*)d_in[4];
    const float* We_p   = (const float*)d_in[5];
    const float* Oe_p   = (const float*)d_in[6];
    float* out = (float*)d_out;

    qkv_kernel <<<NB*NN/8, 384>>>(n_in_p, Wqkv_p);
    edge_kernel<<<NB*NN,   256>>>(e_p, Wg_p, We_p, Oe_p, out + NB*NN*DDIM);
    attn_kernel<<<NB*NN,   256>>>();
    nout_kernel<<<NB*NN/8, 128>>>(On_p, out);
}

// round 4
// speedup vs baseline: 1.9138x; 1.9138x over previous
#include <cuda_runtime.h>

#define NB   2
#define NN   512
#define DDIM 128
#define HH   8

// ---------------------------------------------------------------------------
// Scratch (device globals — no allocation allowed)
// ---------------------------------------------------------------------------
__device__ __align__(128) float g_qkv [NB*NN*384];          // Q at [tok][0..128), K at [128..256)
__device__ __align__(128) float g_vt  [NB*HH*16*NN];        // V transposed: [b][h][dk][m]
__device__ __align__(128) float g_Ebuf[(size_t)NB*NN*NN*HH];// scores then _E, layout [b][n][m][h]
__device__ __align__(128) float g_gsum[NB*HH*NN];           // sum_m sigmoid(G)

// ---------------------------------------------------------------------------
// Packed f32x2 helpers (Blackwell dual FP32)
// ---------------------------------------------------------------------------
__device__ __forceinline__ unsigned long long fma2(unsigned long long a,
                                                   unsigned long long b,
                                                   unsigned long long c) {
    unsigned long long d;
    asm("fma.rn.f32x2 %0, %1, %2, %3;" : "=l"(d) : "l"(a), "l"(b), "l"(c));
    return d;
}
__device__ __forceinline__ unsigned long long pack2(float x) {
    unsigned long long d;
    asm("mov.b64 %0, {%1, %1};" : "=l"(d) : "f"(x));
    return d;
}
__device__ __forceinline__ void unpack2(unsigned long long v, float& lo, float& hi) {
    asm("mov.b64 {%0, %1}, %2;" : "=f"(lo), "=f"(hi) : "l"(v));
}

// ---------------------------------------------------------------------------
// Kernel 1: qkv = n @ W_qkv.  Q,K -> g_qkv ; V -> g_vt transposed.
// ---------------------------------------------------------------------------
__global__ void __launch_bounds__(384) qkv_kernel(const float* __restrict__ nin,
                                                  const float* __restrict__ Wqkv)
{
    __shared__ float sA[8*128];
    const int tid = threadIdx.x;
    const int r0  = blockIdx.x * 8;
    for (int i = tid; i < 1024; i += 384) sA[i] = nin[(size_t)r0*128 + i];
    __syncthreads();
    float acc[8] = {0,0,0,0,0,0,0,0};
    const int c = tid;
#pragma unroll 4
    for (int d = 0; d < 128; d++) {
        const float wv = Wqkv[d*384 + c];
#pragma unroll
        for (int r = 0; r < 8; r++) acc[r] += sA[r*128 + d] * wv;
    }
    const int b = r0 >> 9;
#pragma unroll
    for (int r = 0; r < 8; r++) {
        const int tok = r0 + r;
        if (c < 256) g_qkv[(size_t)tok*384 + c] = acc[r];
        else         g_vt[(size_t)(b*128 + (c - 256))*NN + (tok & 511)] = acc[r];
    }
}

// ---------------------------------------------------------------------------
// Kernel 2: scores = clip(Q.K * DK^-0.5) -> g_Ebuf[bn][m][h]; zero g_gsum.
// Block covers 4 n (same b); K staged in 64-row chunks.
// ---------------------------------------------------------------------------
__global__ void __launch_bounds__(256) scores_kernel()
{
    __shared__ __align__(16) float sK[64*132];
    __shared__ __align__(16) float sQ[4*132];
    const int tid = threadIdx.x;
    const int bn0 = blockIdx.x * 4;
    const int b   = bn0 >> 9, n0 = bn0 & 511;

    if (tid < 32) {
        const int nl = tid >> 3, h = tid & 7;
        g_gsum[(b*8 + h)*NN + n0 + nl] = 0.f;
    }
    if (tid < 128) {
        const int nl = tid >> 5, c = tid & 31;
        ((float4*)sQ)[nl*33 + c] = *((const float4*)(g_qkv + (size_t)(bn0+nl)*384) + c);
    }

    const int h  = tid & 7;
    const int ml = tid >> 3;
    float4* sK4 = (float4*)sK;
    const float4* sQ4 = (const float4*)sQ;

    for (int chunk = 0; chunk < 8; chunk++) {
        const int mb = chunk * 64;
        __syncthreads();
#pragma unroll
        for (int it = 0; it < 8; it++) {
            const int i = it*256 + tid;
            const int rr = i >> 5, c = i & 31;
            sK4[rr*33 + c] =
                *((const float4*)(g_qkv + ((size_t)(b*NN + mb + rr)*384 + 128)) + c);
        }
        __syncthreads();
#pragma unroll
        for (int mm = 0; mm < 2; mm++) {
            const int m = ml + mm*32;
            const float4 k0 = sK4[m*33 + h*4 + 0];
            const float4 k1 = sK4[m*33 + h*4 + 1];
            const float4 k2 = sK4[m*33 + h*4 + 2];
            const float4 k3 = sK4[m*33 + h*4 + 3];
#pragma unroll
            for (int nl = 0; nl < 4; nl++) {
                const float4 q0 = sQ4[nl*33 + h*4 + 0];
                const float4 q1 = sQ4[nl*33 + h*4 + 1];
                const float4 q2 = sQ4[nl*33 + h*4 + 2];
                const float4 q3 = sQ4[nl*33 + h*4 + 3];
                float d = q0.x*k0.x + q0.y*k0.y + q0.z*k0.z + q0.w*k0.w
                        + q1.x*k1.x + q1.y*k1.y + q1.z*k1.z + q1.w*k1.w
                        + q2.x*k2.x + q2.y*k2.y + q2.z*k2.z + q2.w*k2.w
                        + q3.x*k3.x + q3.y*k3.y + q3.z*k3.z + q3.w*k3.w;
                d = fminf(fmaxf(d * 0.25f, -5.f), 5.f);
                g_Ebuf[((size_t)(bn0+nl)*NN + mb + m)*8 + h] = d;
            }
        }
    }
}

// ---------------------------------------------------------------------------
// Kernel 3: fused edge pass.  64 e-rows per block (128 thr, lane-pair per row,
// k split 64/64).  Phase1: EG projection (f32x2), + precomputed score -> _E
// (write back to g_Ebuf), G sigmoid-sum.  Phase2: e_out row = _E @ O_e into
// the (warp-private) e-tile smem, then coalesced streaming store.
// ---------------------------------------------------------------------------
__global__ void __launch_bounds__(128) edge_kernel(const float* __restrict__ e,
                                                   const float* __restrict__ Wg,
                                                   const float* __restrict__ We,
                                                   const float* __restrict__ Oe,
                                                   float* __restrict__ eout)
{
    __shared__ __align__(16) float sE  [64*132];   // e tile -> reused for e_out
    __shared__ __align__(16) float sWEG[128*16];   // [k][ We(8) | Wg(8) ]
    __shared__ __align__(16) float sOe [1024];     // [h][128]
    __shared__ float sGs[8];

    const int tid  = threadIdx.x;
    const int bid  = blockIdx.x;
    const int bn   = bid >> 3;
    const int mbase = (bid & 7) * 64;
    const size_t rowbase = (size_t)bn * NN + mbase;

    for (int i = tid; i < 1024; i += 128) {
        const int d = i >> 3, h = i & 7;
        sWEG[d*16 + h]     = We[i];
        sWEG[d*16 + 8 + h] = Wg[i];
        sOe[i] = Oe[i];
    }
    if (tid < 8) sGs[tid] = 0.f;

    {   // stage e tile, coalesced, streaming
        const float4* esrc = (const float4*)(e + rowbase * DDIM);
        float4* sE4 = (float4*)sE;
#pragma unroll
        for (int it = 0; it < 16; it++) {
            const int i = it*128 + tid;
            const int r = i >> 5, c = i & 31;
            sE4[r*33 + c] = __ldcs(esrc + i);
        }
    }
    __syncthreads();

    const int r = tid >> 1, half = tid & 1, lane = tid & 31;
    const size_t R = rowbase + r;

    // --- phase 1: EG projection over this lane's 64 k ---
    unsigned long long aE0=0,aE1=0,aE2=0,aE3=0,aG0=0,aG1=0,aG2=0,aG3=0;
    {
        const float4* ep = (const float4*)sE + r*33 + half*16;
        const ulonglong2* wu = (const ulonglong2*)sWEG + half*256;  // 4 u2 per k
#pragma unroll 4
        for (int k4 = 0; k4 < 16; k4++) {
            const float4 ev = ep[k4];
            const float ev4[4] = {ev.x, ev.y, ev.z, ev.w};
#pragma unroll
            for (int j = 0; j < 4; j++) {
                const unsigned long long e2 = pack2(ev4[j]);
                const ulonglong2* wk = wu + (k4*4 + j)*4;
                const ulonglong2 wa = wk[0], wb = wk[1], wc = wk[2], wd = wk[3];
                aE0 = fma2(e2, wa.x, aE0); aE1 = fma2(e2, wa.y, aE1);
                aE2 = fma2(e2, wb.x, aE2); aE3 = fma2(e2, wb.y, aE3);
                aG0 = fma2(e2, wc.x, aG0); aG1 = fma2(e2, wc.y, aG1);
                aG2 = fma2(e2, wd.x, aG2); aG3 = fma2(e2, wd.y, aG3);
            }
        }
    }
    float accE[8], accG[8];
    unpack2(aE0, accE[0], accE[1]); unpack2(aE1, accE[2], accE[3]);
    unpack2(aE2, accE[4], accE[5]); unpack2(aE3, accE[6], accE[7]);
    unpack2(aG0, accG[0], accG[1]); unpack2(aG1, accG[2], accG[3]);
    unpack2(aG2, accG[4], accG[5]); unpack2(aG3, accG[6], accG[7]);
#pragma unroll
    for (int h = 0; h < 8; h++) {
        accE[h] += __shfl_xor_sync(0xffffffffu, accE[h], 1);
        accG[h] += __shfl_xor_sync(0xffffffffu, accG[h], 1);
    }

    // add precomputed clipped score -> _E
    float Ef[8];
    {
        const float4* sp = (const float4*)(g_Ebuf + R*8);
        const float4 s0 = sp[0], s1 = sp[1];
        Ef[0]=accE[0]+s0.x; Ef[1]=accE[1]+s0.y; Ef[2]=accE[2]+s0.z; Ef[3]=accE[3]+s0.w;
        Ef[4]=accE[4]+s1.x; Ef[5]=accE[5]+s1.y; Ef[6]=accE[6]+s1.z; Ef[7]=accE[7]+s1.w;
    }
    if (half == 0) {   // write back _E for the attention kernel
        float4* dp = (float4*)(g_Ebuf + R*8);
        dp[0] = make_float4(Ef[0], Ef[1], Ef[2], Ef[3]);
        dp[1] = make_float4(Ef[4], Ef[5], Ef[6], Ef[7]);
    }

    // G sigmoid sums (half==0 lanes contribute, reduce across warp)
#pragma unroll
    for (int h = 0; h < 8; h++) {
        float sg = half ? 0.f : 1.f / (1.f + __expf(-accG[h]));
        sg += __shfl_xor_sync(0xffffffffu, sg, 1);
        sg += __shfl_xor_sync(0xffffffffu, sg, 2);
        sg += __shfl_xor_sync(0xffffffffu, sg, 4);
        sg += __shfl_xor_sync(0xffffffffu, sg, 8);
        sg += __shfl_xor_sync(0xffffffffu, sg, 16);
        if (lane == 0) atomicAdd(&sGs[h], sg);
    }

    // --- phase 2: e_out row (rank-8) into warp-private smem rows ---
    {
        unsigned long long efp[8];
#pragma unroll
        for (int h = 0; h < 8; h++) efp[h] = pack2(Ef[h]);
        const ulonglong2* oeu = (const ulonglong2*)sOe;
        ulonglong2* orow = (ulonglong2*)(sE + r*132);
        const int cbase = half * 16;
#pragma unroll
        for (int c = 0; c < 16; c++) {
            unsigned long long ax = 0ull, ay = 0ull;
#pragma unroll
            for (int h = 0; h < 8; h++) {
                const ulonglong2 ov = oeu[h*32 + cbase + c];
                ax = fma2(efp[h], ov.x, ax);
                ay = fma2(efp[h], ov.y, ay);
            }
            ulonglong2 st; st.x = ax; st.y = ay;
            orow[cbase + c] = st;
        }
    }
    __syncwarp();
    {   // coalesced streaming store of this warp's 16 rows
        const int wbase = (tid >> 5) * 16;
        const float4* sE4 = (const float4*)sE;
        float4* dst = (float4*)eout + (rowbase + wbase)*32;
#pragma unroll
        for (int rr = 0; rr < 16; rr++) {
            const float4 v = sE4[(wbase + rr)*33 + lane];
            __stcs(dst + rr*32 + lane, v);
        }
    }
    __syncthreads();
    if (tid < 8) {
        const int b = bn >> 9, n = bn & 511;
        atomicAdd(&g_gsum[(b*8 + tid)*NN + n], sGs[tid]);
    }
}

// ---------------------------------------------------------------------------
// Kernel 4: softmax(_E) @ V (transposed layout) * log1p(Gsum), then fused
// n_out = n_mid @ O_n.  Block per (b,n), warp per head.
// ---------------------------------------------------------------------------
__global__ void __launch_bounds__(256) attn_kernel(const float* __restrict__ On,
                                                   float* __restrict__ out)
{
    __shared__ float sE[8*520];
    __shared__ float nmid[128];
    __shared__ float pacc[128];
    const int tid = threadIdx.x, bn = blockIdx.x;
    const int b = bn >> 9, n = bn & 511;

    const float4* Eb = (const float4*)(g_Ebuf + (size_t)bn*4096);
    for (int i = tid; i < 1024; i += 256) {
        const float4 v = Eb[i];
        const int m = i >> 1, h0 = (i & 1) * 4;
        sE[(h0+0)*520 + m] = v.x;
        sE[(h0+1)*520 + m] = v.y;
        sE[(h0+2)*520 + m] = v.z;
        sE[(h0+3)*520 + m] = v.w;
    }
    __syncthreads();

    const int h = tid >> 5, lane = tid & 31;
    float x[16];
#pragma unroll
    for (int k = 0; k < 16; k++) x[k] = sE[h*520 + lane + k*32];

    float mx = x[0];
#pragma unroll
    for (int k = 1; k < 16; k++) mx = fmaxf(mx, x[k]);
#pragma unroll
    for (int off = 16; off > 0; off >>= 1)
        mx = fmaxf(mx, __shfl_xor_sync(0xffffffffu, mx, off));

    float p[16]; float s = 0.f;
#pragma unroll
    for (int k = 0; k < 16; k++) { p[k] = __expf(x[k] - mx); s += p[k]; }
#pragma unroll
    for (int off = 16; off > 0; off >>= 1)
        s += __shfl_xor_sync(0xffffffffu, s, off);

    // A @ V with transposed V: contiguous loads per (h,d)
    const float* vb = g_vt + (size_t)(b*128 + h*16)*NN + lane;
    float o[16];
#pragma unroll
    for (int d = 0; d < 16; d++) {
        const float* vr = vb + d*NN;
        float a = 0.f;
#pragma unroll
        for (int k = 0; k < 16; k++) a += p[k] * vr[k*32];
        o[d] = a;
    }
#pragma unroll
    for (int off = 16; off > 0; off >>= 1) {
#pragma unroll
        for (int d = 0; d < 16; d++)
            o[d] += __shfl_xor_sync(0xffffffffu, o[d], off);
    }
    if (lane == 0) {
        const float dc = log1pf(g_gsum[(b*8 + h)*NN + n]);
        const float sc = dc / s;
#pragma unroll
        for (int d = 0; d < 16; d++) nmid[h*16 + d] = o[d] * sc;
    }
    __syncthreads();

    // fused n_out = n_mid @ O_n (two half-dots per column)
    const int c = tid & 127, part = tid >> 7;
    float a = 0.f;
    const float* onp = On + (size_t)(part*64)*128 + c;
#pragma unroll 8
    for (int d = 0; d < 64; d++) a += nmid[part*64 + d] * onp[(size_t)d*128];
    if (part == 1) pacc[c] = a;
    __syncthreads();
    if (part == 0) out[(size_t)bn*128 + c] = a + pacc[c];
}

// ---------------------------------------------------------------------------
// Launch: inputs: n, e, W_qkv, O_n, W_g, W_e, O_e.
// Output: n_out (131072 floats) then e_out (67108864 floats).
// ---------------------------------------------------------------------------
extern "C" void kernel_launch(void* const* d_in, const int* in_sizes, int n_in,
                              void* d_out, int out_size)
{
    const float* n_in_p = (const float*)d_in[0];
    const float* e_p    = (const float*)d_in[1];
    const float* Wqkv_p = (const float*)d_in[2];
    const float* On_p   = (const float*)d_in[3];
    const float* Wg_p   = (const float*)d_in[4];
    const float* We_p   = (const float*)d_in[5];
    const float* Oe_p   = (const float*)d_in[6];
    float* out = (float*)d_out;

    qkv_kernel   <<<NB*NN/8, 384>>>(n_in_p, Wqkv_p);
    scores_kernel<<<NB*NN/4, 256>>>();
    edge_kernel  <<<NB*NN*8, 128>>>(e_p, Wg_p, We_p, Oe_p, out + NB*NN*DDIM);
    attn_kernel  <<<NB*NN,   256>>>(On_p, out);
}